// round 13
// baseline (speedup 1.0000x reference)
#include <cuda_runtime.h>
#include <cuda_bf16.h>
#include <math.h>
#include <stdint.h>

#define B_     32
#define N_     256
#define DIM_   384
#define H_     6
#define DH_    64
#define MLP_   1536
#define DEPTH_ 12
#define INNER_ 384
#define TOK_   (B_*N_)      // 8192 tokens
#define QKVLD_ 1152         // q(384) | k(384) | v(384)

// ---------------- scratch (device globals; no allocation allowed) -------------
__device__ __align__(16) __nv_bfloat16 g_y_h[TOK_*DIM_];
__device__ __align__(16) __nv_bfloat16 g_y_l[TOK_*DIM_];
__device__ float g_qkv[TOK_*QKVLD_];                // fused q|k|v per token (fp32)
__device__ float g_dots[(size_t)B_*H_*N_*N_];
__device__ float g_attn[(size_t)B_*H_*N_*N_];
__device__ __align__(16) __nv_bfloat16 g_o_h[TOK_*INNER_];
__device__ __align__(16) __nv_bfloat16 g_o_l[TOK_*INNER_];
__device__ __align__(16) __nv_bfloat16 g_h_h[TOK_*MLP_];
__device__ __align__(16) __nv_bfloat16 g_h_l[TOK_*MLP_];
// pre-split weights (hi/lo bf16); wq+wkv packed into one [DIM x 1152] per layer
__device__ __align__(16) __nv_bfloat16 g_wqkv_h[DEPTH_*DIM_*QKVLD_];
__device__ __align__(16) __nv_bfloat16 g_wqkv_l[DEPTH_*DIM_*QKVLD_];
__device__ __align__(16) __nv_bfloat16 g_wo_h[DEPTH_*INNER_*DIM_];
__device__ __align__(16) __nv_bfloat16 g_wo_l[DEPTH_*INNER_*DIM_];
__device__ __align__(16) __nv_bfloat16 g_w1_h[DEPTH_*DIM_*MLP_];
__device__ __align__(16) __nv_bfloat16 g_w1_l[DEPTH_*DIM_*MLP_];
__device__ __align__(16) __nv_bfloat16 g_w2_h[DEPTH_*MLP_*DIM_];
__device__ __align__(16) __nv_bfloat16 g_w2_l[DEPTH_*MLP_*DIM_];

__device__ __forceinline__ void bsplit(float v, __nv_bfloat16& h, __nv_bfloat16& l) {
    h = __float2bfloat16_rn(v);
    l = __float2bfloat16_rn(v - __bfloat162float(h));
}

// ---------------- fp32 -> bf16 hi/lo split (plain) -----------------------------
__global__ void split_kernel(const float* __restrict__ src,
                             __nv_bfloat16* __restrict__ hi,
                             __nv_bfloat16* __restrict__ lo, int n) {
    int i = blockIdx.x * 256 + threadIdx.x;
    int stride = gridDim.x * 256;
    for (; i < n; i += stride) {
        __nv_bfloat16 h, l; bsplit(src[i], h, l);
        hi[i] = h; lo[i] = l;
    }
}

// ---------------- fp32 -> bf16 hi/lo split + pack into [DIM x 1152] ------------
__global__ void pack_split_kernel(const float* __restrict__ src,
                                  __nv_bfloat16* __restrict__ hi,
                                  __nv_bfloat16* __restrict__ lo,
                                  int src_cols, int dst_off, int n) {
    int i = blockIdx.x * 256 + threadIdx.x;
    int stride = gridDim.x * 256;
    int per_layer = DIM_ * src_cols;
    for (; i < n; i += stride) {
        int layer = i / per_layer, rem = i % per_layer;
        int row = rem / src_cols, col = rem % src_cols;
        size_t dst = ((size_t)layer * DIM_ + row) * QKVLD_ + dst_off + col;
        __nv_bfloat16 h, l; bsplit(src[i], h, l);
        hi[dst] = h; lo[dst] = l;
    }
}

// ---------------- LayerNorm -> hi/lo bf16 --------------------------------------
__global__ void ln_kernel(const float* __restrict__ x, const float* __restrict__ g,
                          const float* __restrict__ bta,
                          __nv_bfloat16* __restrict__ yh,
                          __nv_bfloat16* __restrict__ yl) {
    int t = blockIdx.x;
    int tid = threadIdx.x;
    const float* xr = x + (size_t)t * DIM_;
    float v0 = xr[tid], v1 = xr[tid + 128], v2 = xr[tid + 256];
    __shared__ float red[4];

    float s = v0 + v1 + v2;
    #pragma unroll
    for (int o = 16; o > 0; o >>= 1) s += __shfl_xor_sync(0xffffffffu, s, o);
    if ((tid & 31) == 0) red[tid >> 5] = s;
    __syncthreads();
    float mean = (red[0] + red[1] + red[2] + red[3]) * (1.0f / DIM_);
    __syncthreads();

    float d0 = v0 - mean, d1 = v1 - mean, d2 = v2 - mean;
    float q = d0*d0 + d1*d1 + d2*d2;
    #pragma unroll
    for (int o = 16; o > 0; o >>= 1) q += __shfl_xor_sync(0xffffffffu, q, o);
    if ((tid & 31) == 0) red[tid >> 5] = q;
    __syncthreads();
    float var = (red[0] + red[1] + red[2] + red[3]) * (1.0f / DIM_);
    float inv = rsqrtf(var + 1e-5f);

    size_t base = (size_t)t * DIM_;
    #pragma unroll
    for (int e = 0; e < 3; e++) {
        int d = tid + e * 128;
        float val = ((e == 0 ? v0 : e == 1 ? v1 : v2) - mean) * inv * g[d] + bta[d];
        __nv_bfloat16 h, l; bsplit(val, h, l);
        yh[base + d] = h;
        yl[base + d] = l;
    }
}

// ======================= bf16x3 tensor-core GEMM (3-stage pipeline) ============
// EPI: 0 = fp32 store, 1 = bias + exact GELU -> hi/lo bf16, 2 = C += (acc+bias)*ls

#define KC        32
#define A_ROWB    80
#define B_ROWB    272
#define OFF_AH    0
#define OFF_AL    10240
#define OFF_BH    20480
#define OFF_BL    29184
#define STAGE_B   37888
#define NSTAGE    3
#define SMEM_BYTES (NSTAGE*STAGE_B)   // 113664

__device__ __forceinline__ uint32_t sm_u32(const void* p) {
    return (uint32_t)__cvta_generic_to_shared(p);
}
__device__ __forceinline__ void cp16(uint32_t s, const void* g) {
    asm volatile("cp.async.cg.shared.global [%0],[%1],16;\n" :: "r"(s), "l"(g));
}
__device__ __forceinline__ void ldsm_x4(uint32_t* r, uint32_t a) {
    asm volatile("ldmatrix.sync.aligned.m8n8.x4.shared.b16 {%0,%1,%2,%3},[%4];"
                 : "=r"(r[0]), "=r"(r[1]), "=r"(r[2]), "=r"(r[3]) : "r"(a));
}
__device__ __forceinline__ void ldsm_x4_t(uint32_t* r, uint32_t a) {
    asm volatile("ldmatrix.sync.aligned.m8n8.x4.trans.shared.b16 {%0,%1,%2,%3},[%4];"
                 : "=r"(r[0]), "=r"(r[1]), "=r"(r[2]), "=r"(r[3]) : "r"(a));
}
__device__ __forceinline__ void mma_bf16(float* d, const uint32_t* a, const uint32_t* b) {
    asm volatile("mma.sync.aligned.m16n8k16.row.col.f32.bf16.bf16.f32 "
                 "{%0,%1,%2,%3},{%4,%5,%6,%7},{%8,%9},{%0,%1,%2,%3};"
                 : "+f"(d[0]), "+f"(d[1]), "+f"(d[2]), "+f"(d[3])
                 : "r"(a[0]), "r"(a[1]), "r"(a[2]), "r"(a[3]),
                   "r"(b[0]), "r"(b[1]));
}

template<int EPI>
__device__ __forceinline__ void gemm_epilogue(
    float v0, float v1, size_t off, int n,
    float* C, __nv_bfloat16* Ch, __nv_bfloat16* Cl,
    const float* bias, const float* ls) {
    if (EPI == 0) {
        C[off] = v0; C[off + 1] = v1;
    } else if (EPI == 1) {
        v0 += bias[n];     v1 += bias[n + 1];
        float g0 = 0.5f * v0 * (1.0f + erff(v0 * 0.70710678118654752f));
        float g1 = 0.5f * v1 * (1.0f + erff(v1 * 0.70710678118654752f));
        __nv_bfloat16 h0, l0, h1, l1;
        bsplit(g0, h0, l0); bsplit(g1, h1, l1);
        Ch[off] = h0; Ch[off + 1] = h1;
        Cl[off] = l0; Cl[off + 1] = l1;
    } else {
        C[off]     += (v0 + bias[n])     * ls[n];
        C[off + 1] += (v1 + bias[n + 1]) * ls[n + 1];
    }
}

template<int EPI>
__global__ __launch_bounds__(256, 2)
void gemm_mma(const __nv_bfloat16* __restrict__ Ah, const __nv_bfloat16* __restrict__ Al,
              const __nv_bfloat16* __restrict__ Bh, const __nv_bfloat16* __restrict__ Bl,
              float* __restrict__ C,
              __nv_bfloat16* __restrict__ Ch, __nv_bfloat16* __restrict__ Cl,
              int K, int lda, int ldb, int ldc,
              const float* __restrict__ bias, const float* __restrict__ ls) {
    extern __shared__ char smem[];
    const uint32_t sbase = sm_u32(smem);

    const int tid = threadIdx.x;
    const int m0 = blockIdx.y * 128, n0 = blockIdx.x * 128;

    const int w = tid >> 5, lane = tid & 31;
    const int wm = (w & 3) * 32, wn = (w >> 2) * 64;
    const uint32_t aLane0 = (uint32_t)((wm + (lane & 15)) * A_ROWB + (lane >> 4) * 16);
    const uint32_t aLane1 = aLane0 + 16 * A_ROWB;
    const int bg = lane >> 3, bl = lane & 7;
    const uint32_t bLane = (uint32_t)(((bg & 1) * 8 + bl) * B_ROWB + (wn + (bg >> 1) * 8) * 2);

    float acc[2][8][4];
    #pragma unroll
    for (int i = 0; i < 2; i++)
        #pragma unroll
        for (int j = 0; j < 8; j++)
            #pragma unroll
            for (int q = 0; q < 4; q++) acc[i][j][q] = 0.0f;

    const int ar0 = tid >> 2, as0 = (tid & 3);
    const int ar1 = (tid + 256) >> 2, as1 = ((tid + 256) & 3);
    const int br0 = tid >> 4, bs0 = (tid & 15);
    const int br1 = (tid + 256) >> 4, bs1 = ((tid + 256) & 15);

    auto load_stage = [&](int k0, int st) {
        uint32_t sa = sbase + st * STAGE_B;
        cp16(sa + OFF_AH + ar0 * A_ROWB + as0 * 16, Ah + (size_t)(m0 + ar0) * lda + k0 + as0 * 8);
        cp16(sa + OFF_AL + ar0 * A_ROWB + as0 * 16, Al + (size_t)(m0 + ar0) * lda + k0 + as0 * 8);
        cp16(sa + OFF_AH + ar1 * A_ROWB + as1 * 16, Ah + (size_t)(m0 + ar1) * lda + k0 + as1 * 8);
        cp16(sa + OFF_AL + ar1 * A_ROWB + as1 * 16, Al + (size_t)(m0 + ar1) * lda + k0 + as1 * 8);
        cp16(sa + OFF_BH + br0 * B_ROWB + bs0 * 16, Bh + (size_t)(k0 + br0) * ldb + n0 + bs0 * 8);
        cp16(sa + OFF_BL + br0 * B_ROWB + bs0 * 16, Bl + (size_t)(k0 + br0) * ldb + n0 + bs0 * 8);
        cp16(sa + OFF_BH + br1 * B_ROWB + bs1 * 16, Bh + (size_t)(k0 + br1) * ldb + n0 + bs1 * 8);
        cp16(sa + OFF_BL + br1 * B_ROWB + bs1 * 16, Bl + (size_t)(k0 + br1) * ldb + n0 + bs1 * 8);
        asm volatile("cp.async.commit_group;\n");
    };

    const int nch = K / KC;
    load_stage(0, 0);
    load_stage(KC, 1);

    int st = 0;
    for (int ch = 0; ch < nch; ch++) {
        asm volatile("cp.async.wait_group 1;\n");
        __syncthreads();
        if (ch + 2 < nch) {
            int st2 = st + 2; if (st2 >= NSTAGE) st2 -= NSTAGE;
            load_stage((ch + 2) * KC, st2);
        }

        const uint32_t sa = sbase + st * STAGE_B;
        #pragma unroll
        for (int kq = 0; kq < 2; kq++) {
            uint32_t aH[2][4], aL[2][4];
            ldsm_x4(aH[0], sa + OFF_AH + aLane0 + kq * 32);
            ldsm_x4(aH[1], sa + OFF_AH + aLane1 + kq * 32);
            ldsm_x4(aL[0], sa + OFF_AL + aLane0 + kq * 32);
            ldsm_x4(aL[1], sa + OFF_AL + aLane1 + kq * 32);
            #pragma unroll
            for (int ni = 0; ni < 4; ni++) {
                uint32_t bH[4], bL[4];
                ldsm_x4_t(bH, sa + OFF_BH + bLane + kq * 16 * B_ROWB + ni * 32);
                ldsm_x4_t(bL, sa + OFF_BL + bLane + kq * 16 * B_ROWB + ni * 32);
                mma_bf16(acc[0][2 * ni],     aH[0], bH + 0);
                mma_bf16(acc[0][2 * ni + 1], aH[0], bH + 2);
                mma_bf16(acc[1][2 * ni],     aH[1], bH + 0);
                mma_bf16(acc[1][2 * ni + 1], aH[1], bH + 2);
                mma_bf16(acc[0][2 * ni],     aH[0], bL + 0);
                mma_bf16(acc[0][2 * ni + 1], aH[0], bL + 2);
                mma_bf16(acc[1][2 * ni],     aH[1], bL + 0);
                mma_bf16(acc[1][2 * ni + 1], aH[1], bL + 2);
                mma_bf16(acc[0][2 * ni],     aL[0], bH + 0);
                mma_bf16(acc[0][2 * ni + 1], aL[0], bH + 2);
                mma_bf16(acc[1][2 * ni],     aL[1], bH + 0);
                mma_bf16(acc[1][2 * ni + 1], aL[1], bH + 2);
            }
        }
        if (++st >= NSTAGE) st = 0;
    }

    const int r = lane >> 2, c2 = (lane & 3) * 2;
    #pragma unroll
    for (int mi = 0; mi < 2; mi++) {
        #pragma unroll
        for (int nj = 0; nj < 8; nj++) {
            int m = m0 + wm + mi * 16 + r;
            int n = n0 + wn + nj * 8 + c2;
            float* d = acc[mi][nj];
            #pragma unroll
            for (int half = 0; half < 2; half++) {
                size_t off = (size_t)(m + half * 8) * ldc + n;
                gemm_epilogue<EPI>(d[half * 2], d[half * 2 + 1], off, n, C, Ch, Cl, bias, ls);
            }
        }
    }
}

// ============ BM=64 variant: 64x128 block tile (for N=384 GEMMs) ===============
#define A64_ROWB  80
#define OFF64_AH  0
#define OFF64_AL  5120
#define OFF64_BH  10240
#define OFF64_BL  18944
#define STAGE64   27648
#define SMEM64    (NSTAGE*STAGE64)   // 82944

template<int EPI>
__global__ __launch_bounds__(256, 2)
void gemm_mma64(const __nv_bfloat16* __restrict__ Ah, const __nv_bfloat16* __restrict__ Al,
                const __nv_bfloat16* __restrict__ Bh, const __nv_bfloat16* __restrict__ Bl,
                float* __restrict__ C,
                __nv_bfloat16* __restrict__ Ch, __nv_bfloat16* __restrict__ Cl,
                int K, int lda, int ldb, int ldc,
                const float* __restrict__ bias, const float* __restrict__ ls) {
    extern __shared__ char smem[];
    const uint32_t sbase = sm_u32(smem);

    const int tid = threadIdx.x;
    const int m0 = blockIdx.y * 64, n0 = blockIdx.x * 128;

    const int w = tid >> 5, lane = tid & 31;
    const int wm = (w & 1) * 32, wn = (w >> 1) * 32;
    const uint32_t aLane0 = (uint32_t)((wm + (lane & 15)) * A64_ROWB + (lane >> 4) * 16);
    const uint32_t aLane1 = aLane0 + 16 * A64_ROWB;
    const int bg = lane >> 3, bl = lane & 7;
    const uint32_t bLane = (uint32_t)(((bg & 1) * 8 + bl) * B_ROWB + (wn + (bg >> 1) * 8) * 2);

    float acc[2][4][4];
    #pragma unroll
    for (int i = 0; i < 2; i++)
        #pragma unroll
        for (int j = 0; j < 4; j++)
            #pragma unroll
            for (int q = 0; q < 4; q++) acc[i][j][q] = 0.0f;

    const int ar = tid >> 2, as = (tid & 3);
    const int br0 = tid >> 4, bs0 = (tid & 15);
    const int br1 = (tid + 256) >> 4, bs1 = ((tid + 256) & 15);

    auto load_stage = [&](int k0, int st) {
        uint32_t sa = sbase + st * STAGE64;
        cp16(sa + OFF64_AH + ar * A64_ROWB + as * 16, Ah + (size_t)(m0 + ar) * lda + k0 + as * 8);
        cp16(sa + OFF64_AL + ar * A64_ROWB + as * 16, Al + (size_t)(m0 + ar) * lda + k0 + as * 8);
        cp16(sa + OFF64_BH + br0 * B_ROWB + bs0 * 16, Bh + (size_t)(k0 + br0) * ldb + n0 + bs0 * 8);
        cp16(sa + OFF64_BL + br0 * B_ROWB + bs0 * 16, Bl + (size_t)(k0 + br0) * ldb + n0 + bs0 * 8);
        cp16(sa + OFF64_BH + br1 * B_ROWB + bs1 * 16, Bh + (size_t)(k0 + br1) * ldb + n0 + bs1 * 8);
        cp16(sa + OFF64_BL + br1 * B_ROWB + bs1 * 16, Bl + (size_t)(k0 + br1) * ldb + n0 + bs1 * 8);
        asm volatile("cp.async.commit_group;\n");
    };

    const int nch = K / KC;
    load_stage(0, 0);
    load_stage(KC, 1);

    int st = 0;
    for (int ch = 0; ch < nch; ch++) {
        asm volatile("cp.async.wait_group 1;\n");
        __syncthreads();
        if (ch + 2 < nch) {
            int st2 = st + 2; if (st2 >= NSTAGE) st2 -= NSTAGE;
            load_stage((ch + 2) * KC, st2);
        }

        const uint32_t sa = sbase + st * STAGE64;
        #pragma unroll
        for (int kq = 0; kq < 2; kq++) {
            uint32_t aH[2][4], aL[2][4];
            ldsm_x4(aH[0], sa + OFF64_AH + aLane0 + kq * 32);
            ldsm_x4(aH[1], sa + OFF64_AH + aLane1 + kq * 32);
            ldsm_x4(aL[0], sa + OFF64_AL + aLane0 + kq * 32);
            ldsm_x4(aL[1], sa + OFF64_AL + aLane1 + kq * 32);
            #pragma unroll
            for (int ni = 0; ni < 2; ni++) {
                uint32_t bH[4], bL[4];
                ldsm_x4_t(bH, sa + OFF64_BH + bLane + kq * 16 * B_ROWB + ni * 32);
                ldsm_x4_t(bL, sa + OFF64_BL + bLane + kq * 16 * B_ROWB + ni * 32);
                mma_bf16(acc[0][2 * ni],     aH[0], bH + 0);
                mma_bf16(acc[0][2 * ni + 1], aH[0], bH + 2);
                mma_bf16(acc[1][2 * ni],     aH[1], bH + 0);
                mma_bf16(acc[1][2 * ni + 1], aH[1], bH + 2);
                mma_bf16(acc[0][2 * ni],     aH[0], bL + 0);
                mma_bf16(acc[0][2 * ni + 1], aH[0], bL + 2);
                mma_bf16(acc[1][2 * ni],     aH[1], bL + 0);
                mma_bf16(acc[1][2 * ni + 1], aH[1], bL + 2);
                mma_bf16(acc[0][2 * ni],     aL[0], bH + 0);
                mma_bf16(acc[0][2 * ni + 1], aL[0], bH + 2);
                mma_bf16(acc[1][2 * ni],     aL[1], bH + 0);
                mma_bf16(acc[1][2 * ni + 1], aL[1], bH + 2);
            }
        }
        if (++st >= NSTAGE) st = 0;
    }

    const int r = lane >> 2, c2 = (lane & 3) * 2;
    #pragma unroll
    for (int mi = 0; mi < 2; mi++) {
        #pragma unroll
        for (int nj = 0; nj < 4; nj++) {
            int m = m0 + wm + mi * 16 + r;
            int n = n0 + wn + nj * 8 + c2;
            float* d = acc[mi][nj];
            #pragma unroll
            for (int half = 0; half < 2; half++) {
                size_t off = (size_t)(m + half * 8) * ldc + n;
                gemm_epilogue<EPI>(d[half * 2], d[half * 2 + 1], off, n, C, Ch, Cl, bias, ls);
            }
        }
    }
}

// ---------------- QK^T batched GEMM: 128x128 tiles, 8x8 register blocking ------
#define QK_ROWF  132
#define QK_MATF  (64*QK_ROWF)                 // floats per tile
#define QK_SMEM  (2*QK_MATF*4)                // 67584 bytes

__global__ __launch_bounds__(256, 2)
void qk_kernel(const float* __restrict__ qkv, float* __restrict__ dots,
               const float* __restrict__ scale) {
    extern __shared__ float qks[];
    float (*Qs)[QK_ROWF] = (float(*)[QK_ROWF])qks;
    float (*Ks)[QK_ROWF] = (float(*)[QK_ROWF])(qks + QK_MATF);

    int bh = blockIdx.z, h = bh % H_;
    const float* Qb = qkv + (size_t)(bh / H_) * N_ * QKVLD_ + h * DH_;
    const float* Kb = Qb + INNER_;
    int i0 = blockIdx.y * 128, j0 = blockIdx.x * 128;
    int tid = threadIdx.x, tx = tid & 15, ty = tid >> 4;
    int lr = tid >> 1, lk0 = (tid & 1) * 32;

    // load 128x64 Q and K tiles transposed to [k][row]
    #pragma unroll
    for (int c = 0; c < 8; c++) {
        int kk = lk0 + c * 4;
        float4 qa = *(const float4*)&Qb[(size_t)(i0 + lr) * QKVLD_ + kk];
        float4 ka = *(const float4*)&Kb[(size_t)(j0 + lr) * QKVLD_ + kk];
        Qs[kk+0][lr]=qa.x; Qs[kk+1][lr]=qa.y; Qs[kk+2][lr]=qa.z; Qs[kk+3][lr]=qa.w;
        Ks[kk+0][lr]=ka.x; Ks[kk+1][lr]=ka.y; Ks[kk+2][lr]=ka.z; Ks[kk+3][lr]=ka.w;
    }
    __syncthreads();

    float acc[8][8];
    #pragma unroll
    for (int i = 0; i < 8; i++)
        #pragma unroll
        for (int j = 0; j < 8; j++) acc[i][j] = 0.0f;

    for (int kk = 0; kk < DH_; kk++) {
        float a[8], b[8];
        float4 a0 = *(const float4*)&Qs[kk][ty * 8];
        float4 a1 = *(const float4*)&Qs[kk][ty * 8 + 4];
        float4 b0 = *(const float4*)&Ks[kk][tx * 8];
        float4 b1 = *(const float4*)&Ks[kk][tx * 8 + 4];
        a[0]=a0.x; a[1]=a0.y; a[2]=a0.z; a[3]=a0.w;
        a[4]=a1.x; a[5]=a1.y; a[6]=a1.z; a[7]=a1.w;
        b[0]=b0.x; b[1]=b0.y; b[2]=b0.z; b[3]=b0.w;
        b[4]=b1.x; b[5]=b1.y; b[6]=b1.z; b[7]=b1.w;
        #pragma unroll
        for (int i = 0; i < 8; i++)
            #pragma unroll
            for (int j = 0; j < 8; j++)
                acc[i][j] = fmaf(a[i], b[j], acc[i][j]);
    }

    float s = scale[h];
    float* D = dots + (size_t)bh * N_ * N_;
    #pragma unroll
    for (int i = 0; i < 8; i++) {
        size_t rowoff = (size_t)(i0 + ty * 8 + i) * N_ + j0 + tx * 8;
        #pragma unroll
        for (int j = 0; j < 8; j++)
            D[rowoff + j] = acc[i][j] * s;
    }
}

// ---------------- fused mix_pre -> diag mask -> softmax -> mix_post ------------
__global__ __launch_bounds__(256)
void mixsm_kernel(const float* __restrict__ dots, float* __restrict__ attn,
                  const float* __restrict__ mp, const float* __restrict__ mq) {
    __shared__ float rowbuf[H_][N_];
    __shared__ float mpS[H_ * H_], mqS[H_ * H_];
    __shared__ float rinv[H_];

    int b = blockIdx.x >> 8, i = blockIdx.x & (N_ - 1);
    int j = threadIdx.x;
    if (j < H_ * H_) { mpS[j] = mp[j]; mqS[j] = mq[j]; }
    __syncthreads();

    const float NEG_INF = __int_as_float(0xff800000);
    float dh[H_];
    #pragma unroll
    for (int h = 0; h < H_; h++)
        dh[h] = dots[(((size_t)b * H_ + h) * N_ + i) * N_ + j];
    #pragma unroll
    for (int g = 0; g < H_; g++) {
        float v = 0.0f;
        #pragma unroll
        for (int h = 0; h < H_; h++) v = fmaf(dh[h], mpS[h * H_ + g], v);
        rowbuf[g][j] = (j == i) ? NEG_INF : v;
    }
    __syncthreads();

    int wid = j >> 5, lane = j & 31;
    if (wid < H_) {
        float m = NEG_INF;
        #pragma unroll
        for (int l = 0; l < 8; l++) m = fmaxf(m, rowbuf[wid][lane + l * 32]);
        #pragma unroll
        for (int o = 16; o > 0; o >>= 1) m = fmaxf(m, __shfl_xor_sync(0xffffffffu, m, o));
        float ssum = 0.0f;
        #pragma unroll
        for (int l = 0; l < 8; l++) {
            float e = __expf(rowbuf[wid][lane + l * 32] - m);
            rowbuf[wid][lane + l * 32] = e;
            ssum += e;
        }
        #pragma unroll
        for (int o = 16; o > 0; o >>= 1) ssum += __shfl_xor_sync(0xffffffffu, ssum, o);
        if (lane == 0) rinv[wid] = 1.0f / ssum;
    }
    __syncthreads();

    float r[H_];
    #pragma unroll
    for (int g = 0; g < H_; g++) r[g] = rowbuf[g][j] * rinv[g];
    #pragma unroll
    for (int h2 = 0; h2 < H_; h2++) {
        float v = 0.0f;
        #pragma unroll
        for (int g = 0; g < H_; g++) v = fmaf(r[g], mqS[g * H_ + h2], v);
        attn[(((size_t)b * H_ + h2) * N_ + i) * N_ + j] = v;
    }
}

// ---------------- AV batched GEMM (64x64, K=256, cp.async 2-stage) -------------
#define AVC       64
#define AV_ROWF   68
#define AV_ROWB   (AV_ROWF*4)
#define AV_MATB   (64*AV_ROWB)
#define AV_STG    (2*AV_MATB)
#define AV_SMEM   (2*AV_STG)   // 69632

__global__ __launch_bounds__(256, 2)
void av_kernel(const float* __restrict__ attn, const float* __restrict__ qkv,
               __nv_bfloat16* __restrict__ oh, __nv_bfloat16* __restrict__ ol) {
    extern __shared__ char smem[];
    const uint32_t sbase = sm_u32(smem);

    int bh = blockIdx.y, b = bh / H_, h = bh % H_;
    const float* Ab = attn + (size_t)bh * N_ * N_;
    const float* Vb = qkv + (size_t)b * N_ * QKVLD_ + 2 * INNER_ + h * DH_;
    int i0 = blockIdx.x * 64;
    int tid = threadIdx.x, tx = tid & 15, ty = tid >> 4;

    const int lrow = tid >> 2, lq = (tid & 3) * 16;

    auto load_stage = [&](int k0, int st) {
        uint32_t sa = sbase + st * AV_STG;
        const float* Arow = Ab + (size_t)(i0 + lrow) * N_ + k0 + lq;
        const float* Vrow = Vb + (size_t)(k0 + lrow) * QKVLD_ + lq;
        #pragma unroll
        for (int ii = 0; ii < 4; ii++) {
            cp16(sa + lrow * AV_ROWB + (lq + ii * 4) * 4, Arow + ii * 4);
            cp16(sa + AV_MATB + lrow * AV_ROWB + (lq + ii * 4) * 4, Vrow + ii * 4);
        }
        asm volatile("cp.async.commit_group;\n");
    };

    float acc[4][4];
    #pragma unroll
    for (int i = 0; i < 4; i++)
        #pragma unroll
        for (int j = 0; j < 4; j++) acc[i][j] = 0.0f;

    load_stage(0, 0);
    const int nch = N_ / AVC;

    for (int ch = 0; ch < nch; ch++) {
        asm volatile("cp.async.wait_group 0;\n");
        __syncthreads();
        if (ch + 1 < nch) load_stage((ch + 1) * AVC, (ch + 1) & 1);

        const float* As = (const float*)(smem + (ch & 1) * AV_STG);
        const float* Vs = (const float*)(smem + (ch & 1) * AV_STG + AV_MATB);
        #pragma unroll 16
        for (int kk = 0; kk < AVC; kk++) {
            float a[4];
            #pragma unroll
            for (int i = 0; i < 4; i++) a[i] = As[(ty * 4 + i) * AV_ROWF + kk];
            float4 bb = *(const float4*)&Vs[kk * AV_ROWF + tx * 4];
            float bv[4] = {bb.x, bb.y, bb.z, bb.w};
            #pragma unroll
            for (int i = 0; i < 4; i++)
                #pragma unroll
                for (int j = 0; j < 4; j++)
                    acc[i][j] = fmaf(a[i], bv[j], acc[i][j]);
        }
    }

    #pragma unroll
    for (int i = 0; i < 4; i++)
        #pragma unroll
        for (int j = 0; j < 4; j++) {
            size_t off = (size_t)(b * N_ + i0 + ty * 4 + i) * INNER_ + h * DH_ + tx * 4 + j;
            float v = acc[i][j];
            __nv_bfloat16 hh, ll; bsplit(v, hh, ll);
            oh[off] = hh;
            ol[off] = ll;
        }
}

// -------------------------------- launcher ------------------------------------
extern "C" void kernel_launch(void* const* d_in, const int* in_sizes, int n_in,
                              void* d_out, int out_size) {
    const float* x_in   = (const float*)d_in[0];
    const float* ln1_g  = (const float*)d_in[1];
    const float* ln1_b  = (const float*)d_in[2];
    const float* wq     = (const float*)d_in[3];
    const float* wkv    = (const float*)d_in[4];
    const float* scale  = (const float*)d_in[5];
    const float* mixpre = (const float*)d_in[6];
    const float* mixpost= (const float*)d_in[7];
    const float* wo     = (const float*)d_in[8];
    const float* bo     = (const float*)d_in[9];
    const float* ls1    = (const float*)d_in[10];
    const float* ln2_g  = (const float*)d_in[11];
    const float* ln2_b  = (const float*)d_in[12];
    const float* w1     = (const float*)d_in[13];
    const float* b1     = (const float*)d_in[14];
    const float* w2     = (const float*)d_in[15];
    const float* b2     = (const float*)d_in[16];
    const float* ls2    = (const float*)d_in[17];

    float* xout = (float*)d_out;

    float *qkv, *dots, *attn;
    __nv_bfloat16 *y_h, *y_l, *o_h, *o_l, *h_h, *h_l;
    __nv_bfloat16 *wqkv_h, *wqkv_l, *wo_h, *wo_l, *w1_h, *w1_l, *w2_h, *w2_l;
    cudaGetSymbolAddress((void**)&qkv,  g_qkv);
    cudaGetSymbolAddress((void**)&dots, g_dots);
    cudaGetSymbolAddress((void**)&attn, g_attn);
    cudaGetSymbolAddress((void**)&y_h, g_y_h);      cudaGetSymbolAddress((void**)&y_l, g_y_l);
    cudaGetSymbolAddress((void**)&o_h, g_o_h);      cudaGetSymbolAddress((void**)&o_l, g_o_l);
    cudaGetSymbolAddress((void**)&h_h, g_h_h);      cudaGetSymbolAddress((void**)&h_l, g_h_l);
    cudaGetSymbolAddress((void**)&wqkv_h, g_wqkv_h); cudaGetSymbolAddress((void**)&wqkv_l, g_wqkv_l);
    cudaGetSymbolAddress((void**)&wo_h, g_wo_h);    cudaGetSymbolAddress((void**)&wo_l, g_wo_l);
    cudaGetSymbolAddress((void**)&w1_h, g_w1_h);    cudaGetSymbolAddress((void**)&w1_l, g_w1_l);
    cudaGetSymbolAddress((void**)&w2_h, g_w2_h);    cudaGetSymbolAddress((void**)&w2_l, g_w2_l);

    cudaFuncSetAttribute(gemm_mma<0>, cudaFuncAttributeMaxDynamicSharedMemorySize, SMEM_BYTES);
    cudaFuncSetAttribute(gemm_mma<1>, cudaFuncAttributeMaxDynamicSharedMemorySize, SMEM_BYTES);
    cudaFuncSetAttribute(gemm_mma64<2>, cudaFuncAttributeMaxDynamicSharedMemorySize, SMEM64);
    cudaFuncSetAttribute(av_kernel, cudaFuncAttributeMaxDynamicSharedMemorySize, AV_SMEM);
    cudaFuncSetAttribute(qk_kernel, cudaFuncAttributeMaxDynamicSharedMemorySize, QK_SMEM);

    // pre-split weights into bf16 hi/lo; wq+wkv packed into one [DIM x 1152]
    pack_split_kernel<<<512, 256>>>(wq,  wqkv_h, wqkv_l, INNER_,     0,      DEPTH_*DIM_*INNER_);
    pack_split_kernel<<<512, 256>>>(wkv, wqkv_h, wqkv_l, 2 * INNER_, INNER_, DEPTH_*DIM_*2*INNER_);
    split_kernel<<<512, 256>>>(wo,  wo_h,  wo_l,  DEPTH_*INNER_*DIM_);
    split_kernel<<<512, 256>>>(w1,  w1_h,  w1_l,  DEPTH_*DIM_*MLP_);
    split_kernel<<<512, 256>>>(w2,  w2_h,  w2_l,  DEPTH_*MLP_*DIM_);

    cudaMemcpyAsync(xout, x_in, (size_t)TOK_ * DIM_ * sizeof(float),
                    cudaMemcpyDeviceToDevice);

    for (int L = 0; L < DEPTH_; L++) {
        // --- attention ---
        ln_kernel<<<TOK_, 128>>>(xout, ln1_g + L * DIM_, ln1_b + L * DIM_, y_h, y_l);
        gemm_mma<0><<<dim3(QKVLD_ / 128, TOK_ / 128), 256, SMEM_BYTES>>>(
            y_h, y_l, wqkv_h + (size_t)L * DIM_ * QKVLD_, wqkv_l + (size_t)L * DIM_ * QKVLD_,
            qkv, nullptr, nullptr, DIM_, DIM_, QKVLD_, QKVLD_, nullptr, nullptr);
        qk_kernel<<<dim3(N_ / 128, N_ / 128, B_ * H_), 256, QK_SMEM>>>(
            qkv, dots, scale + L * H_);
        mixsm_kernel<<<TOK_, 256>>>(dots, attn,
                                    mixpre + L * H_ * H_, mixpost + L * H_ * H_);
        av_kernel<<<dim3(N_ / 64, B_ * H_), 256, AV_SMEM>>>(attn, qkv, o_h, o_l);
        gemm_mma64<2><<<dim3(DIM_ / 128, TOK_ / 64), 256, SMEM64>>>(
            o_h, o_l, wo_h + (size_t)L * INNER_ * DIM_, wo_l + (size_t)L * INNER_ * DIM_,
            xout, nullptr, nullptr, INNER_, INNER_, DIM_, DIM_, bo + L * DIM_, ls1 + L * DIM_);
        // --- MLP ---
        ln_kernel<<<TOK_, 128>>>(xout, ln2_g + L * DIM_, ln2_b + L * DIM_, y_h, y_l);
        gemm_mma<1><<<dim3(MLP_ / 128, TOK_ / 128), 256, SMEM_BYTES>>>(
            y_h, y_l, w1_h + (size_t)L * DIM_ * MLP_, w1_l + (size_t)L * DIM_ * MLP_,
            nullptr, h_h, h_l, DIM_, DIM_, MLP_, MLP_, b1 + L * MLP_, nullptr);
        gemm_mma64<2><<<dim3(DIM_ / 128, TOK_ / 64), 256, SMEM64>>>(
            h_h, h_l, w2_h + (size_t)L * MLP_ * DIM_, w2_l + (size_t)L * MLP_ * DIM_,
            xout, nullptr, nullptr, MLP_, MLP_, DIM_, DIM_, b2 + L * DIM_, ls2 + L * DIM_);
    }
}

// round 14
// speedup vs baseline: 1.0283x; 1.0283x over previous
#include <cuda_runtime.h>
#include <cuda_bf16.h>
#include <math.h>
#include <stdint.h>

#define B_     32
#define N_     256
#define DIM_   384
#define H_     6
#define DH_    64
#define MLP_   1536
#define DEPTH_ 12
#define INNER_ 384
#define TOK_   (B_*N_)      // 8192 tokens
#define QKVLD_ 1152         // q(384) | k(384) | v(384)

// ---------------- scratch (device globals; no allocation allowed) -------------
__device__ __align__(16) __nv_bfloat16 g_y_h[TOK_*DIM_];
__device__ __align__(16) __nv_bfloat16 g_y_l[TOK_*DIM_];
__device__ float g_qkv[TOK_*QKVLD_];                // fused q|k|v per token (fp32)
__device__ float g_dots[(size_t)B_*H_*N_*N_];
__device__ float g_attn[(size_t)B_*H_*N_*N_];
__device__ __align__(16) __nv_bfloat16 g_o_h[TOK_*INNER_];
__device__ __align__(16) __nv_bfloat16 g_o_l[TOK_*INNER_];
__device__ __align__(16) __nv_bfloat16 g_h_h[TOK_*MLP_];
__device__ __align__(16) __nv_bfloat16 g_h_l[TOK_*MLP_];
// pre-split weights (hi/lo bf16); wq+wkv packed into one [DIM x 1152] per layer
__device__ __align__(16) __nv_bfloat16 g_wqkv_h[DEPTH_*DIM_*QKVLD_];
__device__ __align__(16) __nv_bfloat16 g_wqkv_l[DEPTH_*DIM_*QKVLD_];
__device__ __align__(16) __nv_bfloat16 g_wo_h[DEPTH_*INNER_*DIM_];
__device__ __align__(16) __nv_bfloat16 g_wo_l[DEPTH_*INNER_*DIM_];
__device__ __align__(16) __nv_bfloat16 g_w1_h[DEPTH_*DIM_*MLP_];
__device__ __align__(16) __nv_bfloat16 g_w1_l[DEPTH_*DIM_*MLP_];
__device__ __align__(16) __nv_bfloat16 g_w2_h[DEPTH_*MLP_*DIM_];
__device__ __align__(16) __nv_bfloat16 g_w2_l[DEPTH_*MLP_*DIM_];

__device__ __forceinline__ void bsplit(float v, __nv_bfloat16& h, __nv_bfloat16& l) {
    h = __float2bfloat16_rn(v);
    l = __float2bfloat16_rn(v - __bfloat162float(h));
}

// ---------------- fp32 -> bf16 hi/lo split (plain) -----------------------------
__global__ void split_kernel(const float* __restrict__ src,
                             __nv_bfloat16* __restrict__ hi,
                             __nv_bfloat16* __restrict__ lo, int n) {
    int i = blockIdx.x * 256 + threadIdx.x;
    int stride = gridDim.x * 256;
    for (; i < n; i += stride) {
        __nv_bfloat16 h, l; bsplit(src[i], h, l);
        hi[i] = h; lo[i] = l;
    }
}

// ---------------- fp32 -> bf16 hi/lo split + pack into [DIM x 1152] ------------
__global__ void pack_split_kernel(const float* __restrict__ src,
                                  __nv_bfloat16* __restrict__ hi,
                                  __nv_bfloat16* __restrict__ lo,
                                  int src_cols, int dst_off, int n) {
    int i = blockIdx.x * 256 + threadIdx.x;
    int stride = gridDim.x * 256;
    int per_layer = DIM_ * src_cols;
    for (; i < n; i += stride) {
        int layer = i / per_layer, rem = i % per_layer;
        int row = rem / src_cols, col = rem % src_cols;
        size_t dst = ((size_t)layer * DIM_ + row) * QKVLD_ + dst_off + col;
        __nv_bfloat16 h, l; bsplit(src[i], h, l);
        hi[dst] = h; lo[dst] = l;
    }
}

// ---------------- LayerNorm -> hi/lo bf16 (2 tokens per 256-thr block) ---------
__global__ __launch_bounds__(256)
void ln_kernel(const float* __restrict__ x, const float* __restrict__ g,
               const float* __restrict__ bta,
               __nv_bfloat16* __restrict__ yh,
               __nv_bfloat16* __restrict__ yl) {
    const int tid = threadIdx.x;
    const int grp = tid >> 7;            // 0/1
    const int ltid = tid & 127;
    const int t = blockIdx.x * 2 + grp;
    const float* xr = x + (size_t)t * DIM_;
    float v0 = xr[ltid], v1 = xr[ltid + 128], v2 = xr[ltid + 256];
    __shared__ float red[2][4];

    float s = v0 + v1 + v2;
    #pragma unroll
    for (int o = 16; o > 0; o >>= 1) s += __shfl_xor_sync(0xffffffffu, s, o);
    if ((ltid & 31) == 0) red[grp][ltid >> 5] = s;
    __syncthreads();
    float mean = (red[grp][0] + red[grp][1] + red[grp][2] + red[grp][3]) * (1.0f / DIM_);
    __syncthreads();

    float d0 = v0 - mean, d1 = v1 - mean, d2 = v2 - mean;
    float q = d0*d0 + d1*d1 + d2*d2;
    #pragma unroll
    for (int o = 16; o > 0; o >>= 1) q += __shfl_xor_sync(0xffffffffu, q, o);
    if ((ltid & 31) == 0) red[grp][ltid >> 5] = q;
    __syncthreads();
    float var = (red[grp][0] + red[grp][1] + red[grp][2] + red[grp][3]) * (1.0f / DIM_);
    float inv = rsqrtf(var + 1e-5f);

    size_t base = (size_t)t * DIM_;
    #pragma unroll
    for (int e = 0; e < 3; e++) {
        int d = ltid + e * 128;
        float val = ((e == 0 ? v0 : e == 1 ? v1 : v2) - mean) * inv * g[d] + bta[d];
        __nv_bfloat16 h, l; bsplit(val, h, l);
        yh[base + d] = h;
        yl[base + d] = l;
    }
}

// ======================= bf16x3 tensor-core GEMM (3-stage pipeline) ============
// EPI: 0 = fp32 store, 1 = bias + exact GELU -> hi/lo bf16, 2 = C += (acc+bias)*ls

#define KC        32
#define A_ROWB    80
#define B_ROWB    272
#define OFF_AH    0
#define OFF_AL    10240
#define OFF_BH    20480
#define OFF_BL    29184
#define STAGE_B   37888
#define NSTAGE    3
#define SMEM_BYTES (NSTAGE*STAGE_B)   // 113664

__device__ __forceinline__ uint32_t sm_u32(const void* p) {
    return (uint32_t)__cvta_generic_to_shared(p);
}
__device__ __forceinline__ void cp16(uint32_t s, const void* g) {
    asm volatile("cp.async.cg.shared.global [%0],[%1],16;\n" :: "r"(s), "l"(g));
}
__device__ __forceinline__ void ldsm_x4(uint32_t* r, uint32_t a) {
    asm volatile("ldmatrix.sync.aligned.m8n8.x4.shared.b16 {%0,%1,%2,%3},[%4];"
                 : "=r"(r[0]), "=r"(r[1]), "=r"(r[2]), "=r"(r[3]) : "r"(a));
}
__device__ __forceinline__ void ldsm_x4_t(uint32_t* r, uint32_t a) {
    asm volatile("ldmatrix.sync.aligned.m8n8.x4.trans.shared.b16 {%0,%1,%2,%3},[%4];"
                 : "=r"(r[0]), "=r"(r[1]), "=r"(r[2]), "=r"(r[3]) : "r"(a));
}
__device__ __forceinline__ void mma_bf16(float* d, const uint32_t* a, const uint32_t* b) {
    asm volatile("mma.sync.aligned.m16n8k16.row.col.f32.bf16.bf16.f32 "
                 "{%0,%1,%2,%3},{%4,%5,%6,%7},{%8,%9},{%0,%1,%2,%3};"
                 : "+f"(d[0]), "+f"(d[1]), "+f"(d[2]), "+f"(d[3])
                 : "r"(a[0]), "r"(a[1]), "r"(a[2]), "r"(a[3]),
                   "r"(b[0]), "r"(b[1]));
}

template<int EPI>
__device__ __forceinline__ void gemm_epilogue(
    float v0, float v1, size_t off, int n,
    float* C, __nv_bfloat16* Ch, __nv_bfloat16* Cl,
    const float* bias, const float* ls) {
    if (EPI == 0) {
        C[off] = v0; C[off + 1] = v1;
    } else if (EPI == 1) {
        v0 += bias[n];     v1 += bias[n + 1];
        float g0 = 0.5f * v0 * (1.0f + erff(v0 * 0.70710678118654752f));
        float g1 = 0.5f * v1 * (1.0f + erff(v1 * 0.70710678118654752f));
        __nv_bfloat16 h0, l0, h1, l1;
        bsplit(g0, h0, l0); bsplit(g1, h1, l1);
        Ch[off] = h0; Ch[off + 1] = h1;
        Cl[off] = l0; Cl[off + 1] = l1;
    } else {
        C[off]     += (v0 + bias[n])     * ls[n];
        C[off + 1] += (v1 + bias[n + 1]) * ls[n + 1];
    }
}

template<int EPI>
__global__ __launch_bounds__(256, 2)
void gemm_mma(const __nv_bfloat16* __restrict__ Ah, const __nv_bfloat16* __restrict__ Al,
              const __nv_bfloat16* __restrict__ Bh, const __nv_bfloat16* __restrict__ Bl,
              float* __restrict__ C,
              __nv_bfloat16* __restrict__ Ch, __nv_bfloat16* __restrict__ Cl,
              int K, int lda, int ldb, int ldc,
              const float* __restrict__ bias, const float* __restrict__ ls) {
    extern __shared__ char smem[];
    const uint32_t sbase = sm_u32(smem);

    const int tid = threadIdx.x;
    const int m0 = blockIdx.y * 128, n0 = blockIdx.x * 128;

    const int w = tid >> 5, lane = tid & 31;
    const int wm = (w & 3) * 32, wn = (w >> 2) * 64;
    const uint32_t aLane0 = (uint32_t)((wm + (lane & 15)) * A_ROWB + (lane >> 4) * 16);
    const uint32_t aLane1 = aLane0 + 16 * A_ROWB;
    const int bg = lane >> 3, bl = lane & 7;
    const uint32_t bLane = (uint32_t)(((bg & 1) * 8 + bl) * B_ROWB + (wn + (bg >> 1) * 8) * 2);

    float acc[2][8][4];
    #pragma unroll
    for (int i = 0; i < 2; i++)
        #pragma unroll
        for (int j = 0; j < 8; j++)
            #pragma unroll
            for (int q = 0; q < 4; q++) acc[i][j][q] = 0.0f;

    const int ar0 = tid >> 2, as0 = (tid & 3);
    const int ar1 = (tid + 256) >> 2, as1 = ((tid + 256) & 3);
    const int br0 = tid >> 4, bs0 = (tid & 15);
    const int br1 = (tid + 256) >> 4, bs1 = ((tid + 256) & 15);

    auto load_stage = [&](int k0, int st) {
        uint32_t sa = sbase + st * STAGE_B;
        cp16(sa + OFF_AH + ar0 * A_ROWB + as0 * 16, Ah + (size_t)(m0 + ar0) * lda + k0 + as0 * 8);
        cp16(sa + OFF_AL + ar0 * A_ROWB + as0 * 16, Al + (size_t)(m0 + ar0) * lda + k0 + as0 * 8);
        cp16(sa + OFF_AH + ar1 * A_ROWB + as1 * 16, Ah + (size_t)(m0 + ar1) * lda + k0 + as1 * 8);
        cp16(sa + OFF_AL + ar1 * A_ROWB + as1 * 16, Al + (size_t)(m0 + ar1) * lda + k0 + as1 * 8);
        cp16(sa + OFF_BH + br0 * B_ROWB + bs0 * 16, Bh + (size_t)(k0 + br0) * ldb + n0 + bs0 * 8);
        cp16(sa + OFF_BL + br0 * B_ROWB + bs0 * 16, Bl + (size_t)(k0 + br0) * ldb + n0 + bs0 * 8);
        cp16(sa + OFF_BH + br1 * B_ROWB + bs1 * 16, Bh + (size_t)(k0 + br1) * ldb + n0 + bs1 * 8);
        cp16(sa + OFF_BL + br1 * B_ROWB + bs1 * 16, Bl + (size_t)(k0 + br1) * ldb + n0 + bs1 * 8);
        asm volatile("cp.async.commit_group;\n");
    };

    const int nch = K / KC;
    load_stage(0, 0);
    load_stage(KC, 1);

    int st = 0;
    for (int ch = 0; ch < nch; ch++) {
        asm volatile("cp.async.wait_group 1;\n");
        __syncthreads();
        if (ch + 2 < nch) {
            int st2 = st + 2; if (st2 >= NSTAGE) st2 -= NSTAGE;
            load_stage((ch + 2) * KC, st2);
        }

        const uint32_t sa = sbase + st * STAGE_B;
        #pragma unroll
        for (int kq = 0; kq < 2; kq++) {
            uint32_t aH[2][4], aL[2][4];
            ldsm_x4(aH[0], sa + OFF_AH + aLane0 + kq * 32);
            ldsm_x4(aH[1], sa + OFF_AH + aLane1 + kq * 32);
            ldsm_x4(aL[0], sa + OFF_AL + aLane0 + kq * 32);
            ldsm_x4(aL[1], sa + OFF_AL + aLane1 + kq * 32);
            #pragma unroll
            for (int ni = 0; ni < 4; ni++) {
                uint32_t bH[4], bL[4];
                ldsm_x4_t(bH, sa + OFF_BH + bLane + kq * 16 * B_ROWB + ni * 32);
                ldsm_x4_t(bL, sa + OFF_BL + bLane + kq * 16 * B_ROWB + ni * 32);
                mma_bf16(acc[0][2 * ni],     aH[0], bH + 0);
                mma_bf16(acc[0][2 * ni + 1], aH[0], bH + 2);
                mma_bf16(acc[1][2 * ni],     aH[1], bH + 0);
                mma_bf16(acc[1][2 * ni + 1], aH[1], bH + 2);
                mma_bf16(acc[0][2 * ni],     aH[0], bL + 0);
                mma_bf16(acc[0][2 * ni + 1], aH[0], bL + 2);
                mma_bf16(acc[1][2 * ni],     aH[1], bL + 0);
                mma_bf16(acc[1][2 * ni + 1], aH[1], bL + 2);
                mma_bf16(acc[0][2 * ni],     aL[0], bH + 0);
                mma_bf16(acc[0][2 * ni + 1], aL[0], bH + 2);
                mma_bf16(acc[1][2 * ni],     aL[1], bH + 0);
                mma_bf16(acc[1][2 * ni + 1], aL[1], bH + 2);
            }
        }
        if (++st >= NSTAGE) st = 0;
    }

    const int r = lane >> 2, c2 = (lane & 3) * 2;
    #pragma unroll
    for (int mi = 0; mi < 2; mi++) {
        #pragma unroll
        for (int nj = 0; nj < 8; nj++) {
            int m = m0 + wm + mi * 16 + r;
            int n = n0 + wn + nj * 8 + c2;
            float* d = acc[mi][nj];
            #pragma unroll
            for (int half = 0; half < 2; half++) {
                size_t off = (size_t)(m + half * 8) * ldc + n;
                gemm_epilogue<EPI>(d[half * 2], d[half * 2 + 1], off, n, C, Ch, Cl, bias, ls);
            }
        }
    }
}

// ============ BM=64 variant: 64x128 block tile (for N=384 GEMMs) ===============
#define A64_ROWB  80
#define OFF64_AH  0
#define OFF64_AL  5120
#define OFF64_BH  10240
#define OFF64_BL  18944
#define STAGE64   27648
#define SMEM64    (NSTAGE*STAGE64)   // 82944

template<int EPI>
__global__ __launch_bounds__(256, 2)
void gemm_mma64(const __nv_bfloat16* __restrict__ Ah, const __nv_bfloat16* __restrict__ Al,
                const __nv_bfloat16* __restrict__ Bh, const __nv_bfloat16* __restrict__ Bl,
                float* __restrict__ C,
                __nv_bfloat16* __restrict__ Ch, __nv_bfloat16* __restrict__ Cl,
                int K, int lda, int ldb, int ldc,
                const float* __restrict__ bias, const float* __restrict__ ls) {
    extern __shared__ char smem[];
    const uint32_t sbase = sm_u32(smem);

    const int tid = threadIdx.x;
    const int m0 = blockIdx.y * 64, n0 = blockIdx.x * 128;

    const int w = tid >> 5, lane = tid & 31;
    const int wm = (w & 1) * 32, wn = (w >> 1) * 32;
    const uint32_t aLane0 = (uint32_t)((wm + (lane & 15)) * A64_ROWB + (lane >> 4) * 16);
    const uint32_t aLane1 = aLane0 + 16 * A64_ROWB;
    const int bg = lane >> 3, bl = lane & 7;
    const uint32_t bLane = (uint32_t)(((bg & 1) * 8 + bl) * B_ROWB + (wn + (bg >> 1) * 8) * 2);

    float acc[2][4][4];
    #pragma unroll
    for (int i = 0; i < 2; i++)
        #pragma unroll
        for (int j = 0; j < 4; j++)
            #pragma unroll
            for (int q = 0; q < 4; q++) acc[i][j][q] = 0.0f;

    const int ar = tid >> 2, as = (tid & 3);
    const int br0 = tid >> 4, bs0 = (tid & 15);
    const int br1 = (tid + 256) >> 4, bs1 = ((tid + 256) & 15);

    auto load_stage = [&](int k0, int st) {
        uint32_t sa = sbase + st * STAGE64;
        cp16(sa + OFF64_AH + ar * A64_ROWB + as * 16, Ah + (size_t)(m0 + ar) * lda + k0 + as * 8);
        cp16(sa + OFF64_AL + ar * A64_ROWB + as * 16, Al + (size_t)(m0 + ar) * lda + k0 + as * 8);
        cp16(sa + OFF64_BH + br0 * B_ROWB + bs0 * 16, Bh + (size_t)(k0 + br0) * ldb + n0 + bs0 * 8);
        cp16(sa + OFF64_BL + br0 * B_ROWB + bs0 * 16, Bl + (size_t)(k0 + br0) * ldb + n0 + bs0 * 8);
        cp16(sa + OFF64_BH + br1 * B_ROWB + bs1 * 16, Bh + (size_t)(k0 + br1) * ldb + n0 + bs1 * 8);
        cp16(sa + OFF64_BL + br1 * B_ROWB + bs1 * 16, Bl + (size_t)(k0 + br1) * ldb + n0 + bs1 * 8);
        asm volatile("cp.async.commit_group;\n");
    };

    const int nch = K / KC;
    load_stage(0, 0);
    load_stage(KC, 1);

    int st = 0;
    for (int ch = 0; ch < nch; ch++) {
        asm volatile("cp.async.wait_group 1;\n");
        __syncthreads();
        if (ch + 2 < nch) {
            int st2 = st + 2; if (st2 >= NSTAGE) st2 -= NSTAGE;
            load_stage((ch + 2) * KC, st2);
        }

        const uint32_t sa = sbase + st * STAGE64;
        #pragma unroll
        for (int kq = 0; kq < 2; kq++) {
            uint32_t aH[2][4], aL[2][4];
            ldsm_x4(aH[0], sa + OFF64_AH + aLane0 + kq * 32);
            ldsm_x4(aH[1], sa + OFF64_AH + aLane1 + kq * 32);
            ldsm_x4(aL[0], sa + OFF64_AL + aLane0 + kq * 32);
            ldsm_x4(aL[1], sa + OFF64_AL + aLane1 + kq * 32);
            #pragma unroll
            for (int ni = 0; ni < 2; ni++) {
                uint32_t bH[4], bL[4];
                ldsm_x4_t(bH, sa + OFF64_BH + bLane + kq * 16 * B_ROWB + ni * 32);
                ldsm_x4_t(bL, sa + OFF64_BL + bLane + kq * 16 * B_ROWB + ni * 32);
                mma_bf16(acc[0][2 * ni],     aH[0], bH + 0);
                mma_bf16(acc[0][2 * ni + 1], aH[0], bH + 2);
                mma_bf16(acc[1][2 * ni],     aH[1], bH + 0);
                mma_bf16(acc[1][2 * ni + 1], aH[1], bH + 2);
                mma_bf16(acc[0][2 * ni],     aH[0], bL + 0);
                mma_bf16(acc[0][2 * ni + 1], aH[0], bL + 2);
                mma_bf16(acc[1][2 * ni],     aH[1], bL + 0);
                mma_bf16(acc[1][2 * ni + 1], aH[1], bL + 2);
                mma_bf16(acc[0][2 * ni],     aL[0], bH + 0);
                mma_bf16(acc[0][2 * ni + 1], aL[0], bH + 2);
                mma_bf16(acc[1][2 * ni],     aL[1], bH + 0);
                mma_bf16(acc[1][2 * ni + 1], aL[1], bH + 2);
            }
        }
        if (++st >= NSTAGE) st = 0;
    }

    const int r = lane >> 2, c2 = (lane & 3) * 2;
    #pragma unroll
    for (int mi = 0; mi < 2; mi++) {
        #pragma unroll
        for (int nj = 0; nj < 4; nj++) {
            int m = m0 + wm + mi * 16 + r;
            int n = n0 + wn + nj * 8 + c2;
            float* d = acc[mi][nj];
            #pragma unroll
            for (int half = 0; half < 2; half++) {
                size_t off = (size_t)(m + half * 8) * ldc + n;
                gemm_epilogue<EPI>(d[half * 2], d[half * 2 + 1], off, n, C, Ch, Cl, bias, ls);
            }
        }
    }
}

// ---------------- QK^T batched GEMM (64x64 tiles, K=64), single load -----------
__global__ __launch_bounds__(256)
void qk_kernel(const float* __restrict__ qkv, float* __restrict__ dots,
               const float* __restrict__ scale) {
    __shared__ float Qs[64][65];
    __shared__ float Ks[64][65];
    int bh = blockIdx.z, h = bh % H_;
    const float* Qb = qkv + (size_t)(bh / H_) * N_ * QKVLD_ + h * DH_;
    const float* Kb = Qb + INNER_;
    int i0 = blockIdx.y * 64, j0 = blockIdx.x * 64;
    int tid = threadIdx.x, tx = tid & 15, ty = tid >> 4;
    int lr = tid >> 2, lc4 = (tid & 3) * 4;

    #pragma unroll
    for (int k0 = 0; k0 < DH_; k0 += 16) {
        float4 qa = *(const float4*)&Qb[(size_t)(i0 + lr) * QKVLD_ + k0 + lc4];
        float4 ka = *(const float4*)&Kb[(size_t)(j0 + lr) * QKVLD_ + k0 + lc4];
        Qs[k0+lc4+0][lr]=qa.x; Qs[k0+lc4+1][lr]=qa.y; Qs[k0+lc4+2][lr]=qa.z; Qs[k0+lc4+3][lr]=qa.w;
        Ks[k0+lc4+0][lr]=ka.x; Ks[k0+lc4+1][lr]=ka.y; Ks[k0+lc4+2][lr]=ka.z; Ks[k0+lc4+3][lr]=ka.w;
    }
    __syncthreads();

    float acc[4][4];
    #pragma unroll
    for (int i = 0; i < 4; i++)
        #pragma unroll
        for (int j = 0; j < 4; j++) acc[i][j] = 0.0f;

    #pragma unroll 16
    for (int kk = 0; kk < DH_; kk++) {
        float a[4], b[4];
        #pragma unroll
        for (int i = 0; i < 4; i++) a[i] = Qs[kk][ty * 4 + i];
        #pragma unroll
        for (int j = 0; j < 4; j++) b[j] = Ks[kk][tx * 4 + j];
        #pragma unroll
        for (int i = 0; i < 4; i++)
            #pragma unroll
            for (int j = 0; j < 4; j++)
                acc[i][j] = fmaf(a[i], b[j], acc[i][j]);
    }

    float s = scale[h];
    float* D = dots + (size_t)bh * N_ * N_;
    #pragma unroll
    for (int i = 0; i < 4; i++)
        #pragma unroll
        for (int j = 0; j < 4; j++)
            D[(size_t)(i0 + ty * 4 + i) * N_ + j0 + tx * 4 + j] = acc[i][j] * s;
}

// ---------------- fused mix_pre -> diag mask -> softmax -> mix_post ------------
__global__ __launch_bounds__(256)
void mixsm_kernel(const float* __restrict__ dots, float* __restrict__ attn,
                  const float* __restrict__ mp, const float* __restrict__ mq) {
    __shared__ float rowbuf[H_][N_];
    __shared__ float mpS[H_ * H_], mqS[H_ * H_];
    __shared__ float rinv[H_];

    int b = blockIdx.x >> 8, i = blockIdx.x & (N_ - 1);
    int j = threadIdx.x;
    if (j < H_ * H_) { mpS[j] = mp[j]; mqS[j] = mq[j]; }
    __syncthreads();

    const float NEG_INF = __int_as_float(0xff800000);
    float dh[H_];
    #pragma unroll
    for (int h = 0; h < H_; h++)
        dh[h] = dots[(((size_t)b * H_ + h) * N_ + i) * N_ + j];
    #pragma unroll
    for (int g = 0; g < H_; g++) {
        float v = 0.0f;
        #pragma unroll
        for (int h = 0; h < H_; h++) v = fmaf(dh[h], mpS[h * H_ + g], v);
        rowbuf[g][j] = (j == i) ? NEG_INF : v;
    }
    __syncthreads();

    int wid = j >> 5, lane = j & 31;
    if (wid < H_) {
        float m = NEG_INF;
        #pragma unroll
        for (int l = 0; l < 8; l++) m = fmaxf(m, rowbuf[wid][lane + l * 32]);
        #pragma unroll
        for (int o = 16; o > 0; o >>= 1) m = fmaxf(m, __shfl_xor_sync(0xffffffffu, m, o));
        float ssum = 0.0f;
        #pragma unroll
        for (int l = 0; l < 8; l++) {
            float e = __expf(rowbuf[wid][lane + l * 32] - m);
            rowbuf[wid][lane + l * 32] = e;
            ssum += e;
        }
        #pragma unroll
        for (int o = 16; o > 0; o >>= 1) ssum += __shfl_xor_sync(0xffffffffu, ssum, o);
        if (lane == 0) rinv[wid] = 1.0f / ssum;
    }
    __syncthreads();

    float r[H_];
    #pragma unroll
    for (int g = 0; g < H_; g++) r[g] = rowbuf[g][j] * rinv[g];
    #pragma unroll
    for (int h2 = 0; h2 < H_; h2++) {
        float v = 0.0f;
        #pragma unroll
        for (int g = 0; g < H_; g++) v = fmaf(r[g], mqS[g * H_ + h2], v);
        attn[(((size_t)b * H_ + h2) * N_ + i) * N_ + j] = v;
    }
}

// ---------------- AV batched GEMM (64x64, K=256, cp.async 2-stage) -------------
#define AVC       64
#define AV_ROWF   68
#define AV_ROWB   (AV_ROWF*4)
#define AV_MATB   (64*AV_ROWB)
#define AV_STG    (2*AV_MATB)
#define AV_SMEM   (2*AV_STG)   // 69632

__global__ __launch_bounds__(256, 2)
void av_kernel(const float* __restrict__ attn, const float* __restrict__ qkv,
               __nv_bfloat16* __restrict__ oh, __nv_bfloat16* __restrict__ ol) {
    extern __shared__ char smem[];
    const uint32_t sbase = sm_u32(smem);

    int bh = blockIdx.y, b = bh / H_, h = bh % H_;
    const float* Ab = attn + (size_t)bh * N_ * N_;
    const float* Vb = qkv + (size_t)b * N_ * QKVLD_ + 2 * INNER_ + h * DH_;
    int i0 = blockIdx.x * 64;
    int tid = threadIdx.x, tx = tid & 15, ty = tid >> 4;

    const int lrow = tid >> 2, lq = (tid & 3) * 16;

    auto load_stage = [&](int k0, int st) {
        uint32_t sa = sbase + st * AV_STG;
        const float* Arow = Ab + (size_t)(i0 + lrow) * N_ + k0 + lq;
        const float* Vrow = Vb + (size_t)(k0 + lrow) * QKVLD_ + lq;
        #pragma unroll
        for (int ii = 0; ii < 4; ii++) {
            cp16(sa + lrow * AV_ROWB + (lq + ii * 4) * 4, Arow + ii * 4);
            cp16(sa + AV_MATB + lrow * AV_ROWB + (lq + ii * 4) * 4, Vrow + ii * 4);
        }
        asm volatile("cp.async.commit_group;\n");
    };

    float acc[4][4];
    #pragma unroll
    for (int i = 0; i < 4; i++)
        #pragma unroll
        for (int j = 0; j < 4; j++) acc[i][j] = 0.0f;

    load_stage(0, 0);
    const int nch = N_ / AVC;

    for (int ch = 0; ch < nch; ch++) {
        asm volatile("cp.async.wait_group 0;\n");
        __syncthreads();
        if (ch + 1 < nch) load_stage((ch + 1) * AVC, (ch + 1) & 1);

        const float* As = (const float*)(smem + (ch & 1) * AV_STG);
        const float* Vs = (const float*)(smem + (ch & 1) * AV_STG + AV_MATB);
        #pragma unroll 16
        for (int kk = 0; kk < AVC; kk++) {
            float a[4];
            #pragma unroll
            for (int i = 0; i < 4; i++) a[i] = As[(ty * 4 + i) * AV_ROWF + kk];
            float4 bb = *(const float4*)&Vs[kk * AV_ROWF + tx * 4];
            float bv[4] = {bb.x, bb.y, bb.z, bb.w};
            #pragma unroll
            for (int i = 0; i < 4; i++)
                #pragma unroll
                for (int j = 0; j < 4; j++)
                    acc[i][j] = fmaf(a[i], bv[j], acc[i][j]);
        }
    }

    #pragma unroll
    for (int i = 0; i < 4; i++)
        #pragma unroll
        for (int j = 0; j < 4; j++) {
            size_t off = (size_t)(b * N_ + i0 + ty * 4 + i) * INNER_ + h * DH_ + tx * 4 + j;
            float v = acc[i][j];
            __nv_bfloat16 hh, ll; bsplit(v, hh, ll);
            oh[off] = hh;
            ol[off] = ll;
        }
}

// -------------------------------- launcher ------------------------------------
extern "C" void kernel_launch(void* const* d_in, const int* in_sizes, int n_in,
                              void* d_out, int out_size) {
    const float* x_in   = (const float*)d_in[0];
    const float* ln1_g  = (const float*)d_in[1];
    const float* ln1_b  = (const float*)d_in[2];
    const float* wq     = (const float*)d_in[3];
    const float* wkv    = (const float*)d_in[4];
    const float* scale  = (const float*)d_in[5];
    const float* mixpre = (const float*)d_in[6];
    const float* mixpost= (const float*)d_in[7];
    const float* wo     = (const float*)d_in[8];
    const float* bo     = (const float*)d_in[9];
    const float* ls1    = (const float*)d_in[10];
    const float* ln2_g  = (const float*)d_in[11];
    const float* ln2_b  = (const float*)d_in[12];
    const float* w1     = (const float*)d_in[13];
    const float* b1     = (const float*)d_in[14];
    const float* w2     = (const float*)d_in[15];
    const float* b2     = (const float*)d_in[16];
    const float* ls2    = (const float*)d_in[17];

    float* xout = (float*)d_out;

    float *qkv, *dots, *attn;
    __nv_bfloat16 *y_h, *y_l, *o_h, *o_l, *h_h, *h_l;
    __nv_bfloat16 *wqkv_h, *wqkv_l, *wo_h, *wo_l, *w1_h, *w1_l, *w2_h, *w2_l;
    cudaGetSymbolAddress((void**)&qkv,  g_qkv);
    cudaGetSymbolAddress((void**)&dots, g_dots);
    cudaGetSymbolAddress((void**)&attn, g_attn);
    cudaGetSymbolAddress((void**)&y_h, g_y_h);      cudaGetSymbolAddress((void**)&y_l, g_y_l);
    cudaGetSymbolAddress((void**)&o_h, g_o_h);      cudaGetSymbolAddress((void**)&o_l, g_o_l);
    cudaGetSymbolAddress((void**)&h_h, g_h_h);      cudaGetSymbolAddress((void**)&h_l, g_h_l);
    cudaGetSymbolAddress((void**)&wqkv_h, g_wqkv_h); cudaGetSymbolAddress((void**)&wqkv_l, g_wqkv_l);
    cudaGetSymbolAddress((void**)&wo_h, g_wo_h);    cudaGetSymbolAddress((void**)&wo_l, g_wo_l);
    cudaGetSymbolAddress((void**)&w1_h, g_w1_h);    cudaGetSymbolAddress((void**)&w1_l, g_w1_l);
    cudaGetSymbolAddress((void**)&w2_h, g_w2_h);    cudaGetSymbolAddress((void**)&w2_l, g_w2_l);

    cudaFuncSetAttribute(gemm_mma<0>, cudaFuncAttributeMaxDynamicSharedMemorySize, SMEM_BYTES);
    cudaFuncSetAttribute(gemm_mma<1>, cudaFuncAttributeMaxDynamicSharedMemorySize, SMEM_BYTES);
    cudaFuncSetAttribute(gemm_mma64<2>, cudaFuncAttributeMaxDynamicSharedMemorySize, SMEM64);
    cudaFuncSetAttribute(av_kernel, cudaFuncAttributeMaxDynamicSharedMemorySize, AV_SMEM);

    // pre-split weights into bf16 hi/lo; wq+wkv packed into one [DIM x 1152]
    pack_split_kernel<<<512, 256>>>(wq,  wqkv_h, wqkv_l, INNER_,     0,      DEPTH_*DIM_*INNER_);
    pack_split_kernel<<<512, 256>>>(wkv, wqkv_h, wqkv_l, 2 * INNER_, INNER_, DEPTH_*DIM_*2*INNER_);
    split_kernel<<<512, 256>>>(wo,  wo_h,  wo_l,  DEPTH_*INNER_*DIM_);
    split_kernel<<<512, 256>>>(w1,  w1_h,  w1_l,  DEPTH_*DIM_*MLP_);
    split_kernel<<<512, 256>>>(w2,  w2_h,  w2_l,  DEPTH_*MLP_*DIM_);

    cudaMemcpyAsync(xout, x_in, (size_t)TOK_ * DIM_ * sizeof(float),
                    cudaMemcpyDeviceToDevice);

    for (int L = 0; L < DEPTH_; L++) {
        // --- attention ---
        ln_kernel<<<TOK_ / 2, 256>>>(xout, ln1_g + L * DIM_, ln1_b + L * DIM_, y_h, y_l);
        gemm_mma<0><<<dim3(QKVLD_ / 128, TOK_ / 128), 256, SMEM_BYTES>>>(
            y_h, y_l, wqkv_h + (size_t)L * DIM_ * QKVLD_, wqkv_l + (size_t)L * DIM_ * QKVLD_,
            qkv, nullptr, nullptr, DIM_, DIM_, QKVLD_, QKVLD_, nullptr, nullptr);
        qk_kernel<<<dim3(N_ / 64, N_ / 64, B_ * H_), 256>>>(qkv, dots, scale + L * H_);
        mixsm_kernel<<<TOK_, 256>>>(dots, attn,
                                    mixpre + L * H_ * H_, mixpost + L * H_ * H_);
        av_kernel<<<dim3(N_ / 64, B_ * H_), 256, AV_SMEM>>>(attn, qkv, o_h, o_l);
        gemm_mma64<2><<<dim3(DIM_ / 128, TOK_ / 64), 256, SMEM64>>>(
            o_h, o_l, wo_h + (size_t)L * INNER_ * DIM_, wo_l + (size_t)L * INNER_ * DIM_,
            xout, nullptr, nullptr, INNER_, INNER_, DIM_, DIM_, bo + L * DIM_, ls1 + L * DIM_);
        // --- MLP ---
        ln_kernel<<<TOK_ / 2, 256>>>(xout, ln2_g + L * DIM_, ln2_b + L * DIM_, y_h, y_l);
        gemm_mma<1><<<dim3(MLP_ / 128, TOK_ / 128), 256, SMEM_BYTES>>>(
            y_h, y_l, w1_h + (size_t)L * DIM_ * MLP_, w1_l + (size_t)L * DIM_ * MLP_,
            nullptr, h_h, h_l, DIM_, DIM_, MLP_, MLP_, b1 + L * MLP_, nullptr);
        gemm_mma64<2><<<dim3(DIM_ / 128, TOK_ / 64), 256, SMEM64>>>(
            h_h, h_l, w2_h + (size_t)L * MLP_ * DIM_, w2_l + (size_t)L * MLP_ * DIM_,
            xout, nullptr, nullptr, MLP_, MLP_, DIM_, DIM_, b2 + L * DIM_, ls2 + L * DIM_);
    }
}